// round 3
// baseline (speedup 1.0000x reference)
#include <cuda_runtime.h>
#include <cuda_bf16.h>

// Shapes (fixed per reference setup_inputs)
#define B 2
#define S 512
#define T 512
#define D 256
#define H 128
#define BS (B*S)        // 1024
#define BT (B*T)        // 1024

// Scratch (device globals; no allocation allowed)
__device__ float g_src[BS * H];   // LN(source) @ W_su + b_su
__device__ float g_tgt[BT * H];   // LN(target) @ W_tp + b_tp
__device__ float g_A  [BS * H];   // g_src @ W1_s + b1
__device__ float g_C  [BT * H];   // g_tgt @ W1_t

// ---------------------------------------------------------------------------
// Stage 1: per-row layernorm + projection + W1_s / W1_t projection.
// One CTA per row (2048 rows total), 256 threads.
// ---------------------------------------------------------------------------
__global__ __launch_bounds__(256) void norm_proj_kernel(
    const float* __restrict__ sv, const float* __restrict__ tv,
    const float* __restrict__ sng, const float* __restrict__ snb,
    const float* __restrict__ tng, const float* __restrict__ tnb,
    const float* __restrict__ Wsu, const float* __restrict__ bsu,
    const float* __restrict__ Wtp, const float* __restrict__ btp,
    const float* __restrict__ W1,  const float* __restrict__ b1)
{
    __shared__ float xn[D];
    __shared__ float pr[H];
    __shared__ float r1[8], r2[8];

    const int r = blockIdx.x;
    const bool is_src = (r < BS);
    const int row = is_src ? r : r - BS;
    const int tid = threadIdx.x;

    const float* x    = (is_src ? sv : tv) + row * D;
    const float* gv   = is_src ? sng : tng;
    const float* bv   = is_src ? snb : tnb;
    const float* W    = is_src ? Wsu : Wtp;
    const float* bias = is_src ? bsu : btp;

    float v = x[tid];
    float s1 = v, s2 = v * v;
    #pragma unroll
    for (int m = 16; m; m >>= 1) {
        s1 += __shfl_xor_sync(0xffffffffu, s1, m);
        s2 += __shfl_xor_sync(0xffffffffu, s2, m);
    }
    if ((tid & 31) == 0) { r1[tid >> 5] = s1; r2[tid >> 5] = s2; }
    __syncthreads();
    float t1 = 0.f, t2 = 0.f;
    #pragma unroll
    for (int i = 0; i < 8; ++i) { t1 += r1[i]; t2 += r2[i]; }
    const float mean = t1 * (1.0f / D);
    const float var  = t2 * (1.0f / D) - mean * mean;
    const float rs   = rsqrtf(var + 1e-5f);
    xn[tid] = (v - mean) * rs * gv[tid] + bv[tid];
    __syncthreads();

    if (tid < H) {
        float a0 = 0.f, a1 = 0.f, a2 = 0.f, a3 = 0.f;
        #pragma unroll 4
        for (int d = 0; d < D; d += 4) {
            a0 = fmaf(xn[d + 0], W[(d + 0) * H + tid], a0);
            a1 = fmaf(xn[d + 1], W[(d + 1) * H + tid], a1);
            a2 = fmaf(xn[d + 2], W[(d + 2) * H + tid], a2);
            a3 = fmaf(xn[d + 3], W[(d + 3) * H + tid], a3);
        }
        float p = (a0 + a1) + (a2 + a3) + bias[tid];
        pr[tid] = p;
        (is_src ? g_src : g_tgt)[row * H + tid] = p;
    }
    __syncthreads();

    if (tid < H) {
        const float* Wr = W1 + (is_src ? 0 : H * H);
        float a0 = 0.f, a1 = 0.f, a2 = 0.f, a3 = 0.f;
        #pragma unroll 4
        for (int h = 0; h < H; h += 4) {
            a0 = fmaf(pr[h + 0], Wr[(h + 0) * H + tid], a0);
            a1 = fmaf(pr[h + 1], Wr[(h + 1) * H + tid], a1);
            a2 = fmaf(pr[h + 2], Wr[(h + 2) * H + tid], a2);
            a3 = fmaf(pr[h + 3], Wr[(h + 3) * H + tid], a3);
        }
        float p = (a0 + a1) + (a2 + a3) + (is_src ? b1[tid] : 0.0f);
        (is_src ? g_A : g_C)[row * H + tid] = p;
    }
}

// ---------------------------------------------------------------------------
// Stage 2: main fused kernel. One CTA per (b, s). 512 threads (16 warps).
// Per-thread tile: 4 t x 8 k (4 x 4 f32x2 accumulators).
// hidden[t,k] = tgt[t,:] @ (src[s,:] .* W1_st) + A[s,k] + C[t,k]
// score[t]    = sum_k gelu(hidden[t,k]) * W2[k] + b2
// out[b,s,t]  = softsign(score) * mask[b,s]
// ---------------------------------------------------------------------------
#define TT 128   // t-tile
#define NTHR 512

extern __shared__ float smem[];

__global__ __launch_bounds__(NTHR, 1) void edge_main_kernel(
    const float* __restrict__ W1, const float* __restrict__ W2,
    const float* __restrict__ b2p, const int* __restrict__ mask,
    float* __restrict__ out)
{
    float* Wsh  = smem;                 // [H][H] scaled W1_st
    float* Tsh  = smem + H * H;         // [TT][H] target tile
    float* ssrc = smem + 2 * H * H;     // [H]
    float* As   = ssrc + H;             // [H]
    float* w2s  = As + H;               // [H]

    const int bs  = blockIdx.x;        // 0..1023
    const int b   = bs >> 9;
    const int tid = threadIdx.x;

    if (tid < H) {
        ssrc[tid] = g_src[bs * H + tid];
        As[tid]   = g_A[bs * H + tid];
        w2s[tid]  = W2[tid];
    }
    __syncthreads();

    // Wsh[h][k] = src[h] * W1_st[h][k]
    {
        const float4* Wst4 = (const float4*)(W1 + 2 * H * H);
        float4* Wsh4 = (float4*)Wsh;
        #pragma unroll
        for (int i = tid; i < (H * H) / 4; i += NTHR) {
            const int h = i >> 5;         // 32 float4 per row
            float sc = ssrc[h];
            float4 w = Wst4[i];
            w.x *= sc; w.y *= sc; w.z *= sc; w.w *= sc;
            Wsh4[i] = w;
        }
    }

    const float b2v  = b2p[0];
    const float mval = mask[bs] ? 1.0f : 0.0f;

    const int kc = (tid & 15) * 8;   // k base (0..120), 16 groups
    const int tr = (tid >> 4) * 4;   // local t base (0..124), 32 groups

    for (int tt = 0; tt < T / TT; ++tt) {
        const int t0 = tt * TT;
        __syncthreads();   // previous tile readers done before refill

        // Fill Tsh[t][h] = g_tgt[b, t0+t, h]
        {
            const float4* tg4 = (const float4*)(g_tgt + ((b << 9) + t0) * H);
            float4* Tsh4 = (float4*)Tsh;
            #pragma unroll
            for (int i = tid; i < (TT * H) / 4; i += NTHR)
                Tsh4[i] = tg4[i];
        }
        __syncthreads();

        // Mainloop: packed-f32x2 register-tiled GEMM, 4 t x 8 k per thread
        unsigned long long acc[16];
        #pragma unroll
        for (int i = 0; i < 16; ++i) acc[i] = 0ULL;

        #pragma unroll 8
        for (int h = 0; h < H; ++h) {
            unsigned long long a2[4];
            #pragma unroll
            for (int i = 0; i < 4; ++i) {
                float av = Tsh[(tr + i) * H + h];
                asm("mov.b64 %0, {%1, %1};" : "=l"(a2[i]) : "f"(av));
            }
            const ulonglong2* wp = (const ulonglong2*)(&Wsh[h * H + kc]);
            ulonglong2 w01 = wp[0];
            ulonglong2 w23 = wp[1];
            unsigned long long bb[4] = {w01.x, w01.y, w23.x, w23.y};
            #pragma unroll
            for (int i = 0; i < 4; ++i) {
                #pragma unroll
                for (int j = 0; j < 4; ++j)
                    asm("fma.rn.f32x2 %0, %1, %2, %0;"
                        : "+l"(acc[i * 4 + j]) : "l"(a2[i]), "l"(bb[j]));
            }
        }

        // Epilogue: + A + C, exact gelu, dot W2, reduce over 16 k-lanes,
        // softsign, mask, store.
        #pragma unroll
        for (int i = 0; i < 4; ++i) {
            const int t = t0 + tr + i;
            const float4 c0 = *(const float4*)(&g_C[((b << 9) + t) * H + kc]);
            const float4 c1 = *(const float4*)(&g_C[((b << 9) + t) * H + kc + 4]);
            float cc[8] = {c0.x, c0.y, c0.z, c0.w, c1.x, c1.y, c1.z, c1.w};
            float pt = 0.f;
            #pragma unroll
            for (int j2 = 0; j2 < 4; ++j2) {
                float lo, hi;
                asm("mov.b64 {%0, %1}, %2;" : "=f"(lo), "=f"(hi) : "l"(acc[i * 4 + j2]));
                {
                    const int k = kc + 2 * j2;
                    float hv = lo + As[k] + cc[2 * j2];
                    float ge = 0.5f * hv * (1.0f + erff(hv * 0.7071067811865476f));
                    pt = fmaf(ge, w2s[k], pt);
                }
                {
                    const int k = kc + 2 * j2 + 1;
                    float hv = hi + As[k] + cc[2 * j2 + 1];
                    float ge = 0.5f * hv * (1.0f + erff(hv * 0.7071067811865476f));
                    pt = fmaf(ge, w2s[k], pt);
                }
            }
            #pragma unroll
            for (int m = 8; m; m >>= 1)
                pt += __shfl_xor_sync(0xffffffffu, pt, m);
            if ((tid & 15) == 0) {
                const float sc = pt + b2v;
                const float e  = sc / (1.0f + fabsf(sc));
                out[bs * T + t] = e * mval;
            }
        }
    }
}

// ---------------------------------------------------------------------------
extern "C" void kernel_launch(void* const* d_in, const int* in_sizes, int n_in,
                              void* d_out, int out_size)
{
    const float* sv   = (const float*)d_in[0];
    const float* tv   = (const float*)d_in[1];
    const int*   mask = (const int*)d_in[2];
    const float* sng  = (const float*)d_in[3];
    const float* snb  = (const float*)d_in[4];
    const float* tng  = (const float*)d_in[5];
    const float* tnb  = (const float*)d_in[6];
    const float* Wsu  = (const float*)d_in[7];
    const float* bsu  = (const float*)d_in[8];
    const float* Wtp  = (const float*)d_in[9];
    const float* btp  = (const float*)d_in[10];
    const float* W1   = (const float*)d_in[11];
    const float* b1   = (const float*)d_in[12];
    const float* W2   = (const float*)d_in[13];
    const float* b2   = (const float*)d_in[14];
    float* out = (float*)d_out;

    norm_proj_kernel<<<BS + BT, 256>>>(sv, tv, sng, snb, tng, tnb,
                                       Wsu, bsu, Wtp, btp, W1, b1);

    const int smem_bytes = (2 * H * H + 3 * H) * (int)sizeof(float);
    cudaFuncSetAttribute(edge_main_kernel,
                         cudaFuncAttributeMaxDynamicSharedMemorySize, smem_bytes);
    edge_main_kernel<<<BS, NTHR, smem_bytes>>>(W1, W2, b2, mask, out);
}

// round 4
// speedup vs baseline: 2.5773x; 2.5773x over previous
#include <cuda_runtime.h>
#include <cuda_bf16.h>

// Shapes (fixed per reference setup_inputs)
#define B 2
#define S 512
#define T 512
#define D 256
#define H 128
#define BS (B*S)        // 1024
#define BT (B*T)        // 1024

#define PAD 136         // padded row stride (elems) for conflict-free ldmatrix

// Scratch (device globals; no allocation allowed)
__device__ float g_src[BS * H];            // LN(source) @ W_su + b_su (fp32)
__device__ float g_A  [BS * H];            // g_src @ W1_s + b1
__device__ float g_C  [BT * H];            // g_tgt @ W1_t
__device__ __nv_bfloat16 g_thi[BT * H];    // bf16 hi of target proj
__device__ __nv_bfloat16 g_tlo[BT * H];    // bf16 lo (residual)

// ---------------------------------------------------------------------------
// Stage 1: per-row layernorm + projection + W1_s / W1_t projection.
// One CTA per row (2048 rows total), 256 threads.
// ---------------------------------------------------------------------------
__global__ __launch_bounds__(256) void norm_proj_kernel(
    const float* __restrict__ sv, const float* __restrict__ tv,
    const float* __restrict__ sng, const float* __restrict__ snb,
    const float* __restrict__ tng, const float* __restrict__ tnb,
    const float* __restrict__ Wsu, const float* __restrict__ bsu,
    const float* __restrict__ Wtp, const float* __restrict__ btp,
    const float* __restrict__ W1,  const float* __restrict__ b1)
{
    __shared__ float xn[D];
    __shared__ float pr[H];
    __shared__ float r1[8], r2[8];

    const int r = blockIdx.x;
    const bool is_src = (r < BS);
    const int row = is_src ? r : r - BS;
    const int tid = threadIdx.x;

    const float* x    = (is_src ? sv : tv) + row * D;
    const float* gv   = is_src ? sng : tng;
    const float* bv   = is_src ? snb : tnb;
    const float* W    = is_src ? Wsu : Wtp;
    const float* bias = is_src ? bsu : btp;

    float v = x[tid];
    float s1 = v, s2 = v * v;
    #pragma unroll
    for (int m = 16; m; m >>= 1) {
        s1 += __shfl_xor_sync(0xffffffffu, s1, m);
        s2 += __shfl_xor_sync(0xffffffffu, s2, m);
    }
    if ((tid & 31) == 0) { r1[tid >> 5] = s1; r2[tid >> 5] = s2; }
    __syncthreads();
    float t1 = 0.f, t2 = 0.f;
    #pragma unroll
    for (int i = 0; i < 8; ++i) { t1 += r1[i]; t2 += r2[i]; }
    const float mean = t1 * (1.0f / D);
    const float var  = t2 * (1.0f / D) - mean * mean;
    const float rs   = rsqrtf(var + 1e-5f);
    xn[tid] = (v - mean) * rs * gv[tid] + bv[tid];
    __syncthreads();

    if (tid < H) {
        float a0 = 0.f, a1 = 0.f, a2 = 0.f, a3 = 0.f;
        #pragma unroll 4
        for (int d = 0; d < D; d += 4) {
            a0 = fmaf(xn[d + 0], W[(d + 0) * H + tid], a0);
            a1 = fmaf(xn[d + 1], W[(d + 1) * H + tid], a1);
            a2 = fmaf(xn[d + 2], W[(d + 2) * H + tid], a2);
            a3 = fmaf(xn[d + 3], W[(d + 3) * H + tid], a3);
        }
        float p = (a0 + a1) + (a2 + a3) + bias[tid];
        pr[tid] = p;
        if (is_src) {
            g_src[row * H + tid] = p;
        } else {
            __nv_bfloat16 hi = __float2bfloat16(p);
            g_thi[row * H + tid] = hi;
            g_tlo[row * H + tid] = __float2bfloat16(p - __bfloat162float(hi));
        }
    }
    __syncthreads();

    if (tid < H) {
        const float* Wr = W1 + (is_src ? 0 : H * H);
        float a0 = 0.f, a1 = 0.f, a2 = 0.f, a3 = 0.f;
        #pragma unroll 4
        for (int h = 0; h < H; h += 4) {
            a0 = fmaf(pr[h + 0], Wr[(h + 0) * H + tid], a0);
            a1 = fmaf(pr[h + 1], Wr[(h + 1) * H + tid], a1);
            a2 = fmaf(pr[h + 2], Wr[(h + 2) * H + tid], a2);
            a3 = fmaf(pr[h + 3], Wr[(h + 3) * H + tid], a3);
        }
        float p = (a0 + a1) + (a2 + a3) + (is_src ? b1[tid] : 0.0f);
        (is_src ? g_A : g_C)[row * H + tid] = p;
    }
}

// ---------------------------------------------------------------------------
// Stage 2: tensor-core fused kernel. One CTA per (b, s). 256 threads, 8 warps.
// hidden[t,k] = tgt[t,:] @ (src[s,:] .* W1_st) + A[s,k] + C[t,k]   (bf16-split)
// out[b,s,t]  = softsign( sum_k gelu(hidden) * W2[k] + b2 ) * mask
// ---------------------------------------------------------------------------
__device__ __forceinline__ void ldsm_x4(unsigned a, unsigned &r0, unsigned &r1,
                                        unsigned &r2, unsigned &r3) {
    asm volatile("ldmatrix.sync.aligned.m8n8.x4.shared.b16 {%0,%1,%2,%3}, [%4];"
        : "=r"(r0), "=r"(r1), "=r"(r2), "=r"(r3) : "r"(a));
}
__device__ __forceinline__ void ldsm_x4_t(unsigned a, unsigned &r0, unsigned &r1,
                                          unsigned &r2, unsigned &r3) {
    asm volatile("ldmatrix.sync.aligned.m8n8.x4.trans.shared.b16 {%0,%1,%2,%3}, [%4];"
        : "=r"(r0), "=r"(r1), "=r"(r2), "=r"(r3) : "r"(a));
}
__device__ __forceinline__ void mma16816(float* c, const unsigned* a,
                                         unsigned b0, unsigned b1) {
    asm volatile("mma.sync.aligned.m16n8k16.row.col.f32.bf16.bf16.f32 "
        "{%0,%1,%2,%3}, {%4,%5,%6,%7}, {%8,%9}, {%0,%1,%2,%3};"
        : "+f"(c[0]), "+f"(c[1]), "+f"(c[2]), "+f"(c[3])
        : "r"(a[0]), "r"(a[1]), "r"(a[2]), "r"(a[3]), "r"(b0), "r"(b1));
}

// smem byte offsets
#define OFF_WHI 0
#define OFF_WLO (OFF_WHI + H*PAD*2)
#define OFF_THI (OFF_WLO + H*PAD*2)
#define OFF_TLO (OFF_THI + H*PAD*2)
#define OFF_SRC (OFF_TLO + H*PAD*2)
#define OFF_AS  (OFF_SRC + H*4)
#define OFF_W2  (OFF_AS  + H*4)
#define SMEM_BYTES (OFF_W2 + H*4)

extern __shared__ char smem_raw[];

__global__ __launch_bounds__(256, 1) void edge_main_kernel(
    const float* __restrict__ W1, const float* __restrict__ W2,
    const float* __restrict__ b2p, const int* __restrict__ mask,
    float* __restrict__ out)
{
    __nv_bfloat16* Whi = (__nv_bfloat16*)(smem_raw + OFF_WHI);
    __nv_bfloat16* Wlo = (__nv_bfloat16*)(smem_raw + OFF_WLO);
    float* ssrc = (float*)(smem_raw + OFF_SRC);
    float* As   = (float*)(smem_raw + OFF_AS);
    float* w2s  = (float*)(smem_raw + OFF_W2);

    unsigned smem_u32;
    asm("{ .reg .u64 t; cvta.to.shared.u64 t, %1; cvt.u32.u64 %0, t; }"
        : "=r"(smem_u32) : "l"(smem_raw));

    const int bs  = blockIdx.x;
    const int b   = bs >> 9;
    const int tid = threadIdx.x;
    const int wid = tid >> 5;
    const int lane = tid & 31;

    if (tid < H) {
        ssrc[tid] = g_src[bs * H + tid];
        As[tid]   = g_A[bs * H + tid];
        w2s[tid]  = W2[tid];
    }
    __syncthreads();

    // Prologue: Whi/Wlo[h][k] = split( src[h] * W1_st[h][k] ), padded stride
    {
        const float4* Wst4 = (const float4*)(W1 + 2 * H * H);
        for (int i = tid; i < (H * H) / 4; i += 256) {
            const int h = i >> 5;
            const int c = (i & 31) * 4;
            const float sc = ssrc[h];
            float4 w = Wst4[i];
            float v0 = w.x * sc, v1 = w.y * sc, v2 = w.z * sc, v3 = w.w * sc;
            __nv_bfloat16 h0 = __float2bfloat16(v0);
            __nv_bfloat16 h1 = __float2bfloat16(v1);
            __nv_bfloat16 h2 = __float2bfloat16(v2);
            __nv_bfloat16 h3 = __float2bfloat16(v3);
            Whi[h * PAD + c + 0] = h0;  Whi[h * PAD + c + 1] = h1;
            Whi[h * PAD + c + 2] = h2;  Whi[h * PAD + c + 3] = h3;
            Wlo[h * PAD + c + 0] = __float2bfloat16(v0 - __bfloat162float(h0));
            Wlo[h * PAD + c + 1] = __float2bfloat16(v1 - __bfloat162float(h1));
            Wlo[h * PAD + c + 2] = __float2bfloat16(v2 - __bfloat162float(h2));
            Wlo[h * PAD + c + 3] = __float2bfloat16(v3 - __bfloat162float(h3));
        }
    }

    const float b2v  = b2p[0];
    const float mval = mask[bs] ? 1.0f : 0.0f;

    // ldmatrix lane address components (same pattern for A and B operands)
    const int rL = lane & 15;           // row within 16-row span
    const int cL = (lane >> 4) << 3;    // 0 or 8 (col offset)
    const int tw0 = wid * 16;           // warp's t-row base within tile

    for (int tt = 0; tt < T / 128; ++tt) {
        const int gt0 = (b << 9) + tt * 128;   // global target row base
        __syncthreads();

        // Fill Thi/Tlo[t][h] from g_thi/g_tlo (16B chunks, padded stride)
        {
            const uint4* shi = (const uint4*)(g_thi + gt0 * H);
            const uint4* slo = (const uint4*)(g_tlo + gt0 * H);
            for (int i = tid; i < 128 * 16; i += 256) {
                const int row = i >> 4;
                const int c8  = i & 15;
                *(uint4*)(smem_raw + OFF_THI + (row * PAD + c8 * 8) * 2) = shi[row * 16 + c8];
                *(uint4*)(smem_raw + OFF_TLO + (row * PAD + c8 * 8) * 2) = slo[row * 16 + c8];
            }
        }
        __syncthreads();

        // Mainloop: 16t x 128k per warp, K=128 in 8 steps, 3 bf16 passes
        float acc[16][4];
        #pragma unroll
        for (int i = 0; i < 16; ++i)
            #pragma unroll
            for (int j = 0; j < 4; ++j) acc[i][j] = 0.f;

        #pragma unroll
        for (int step = 0; step < 8; ++step) {
            const int h0 = step * 16;
            unsigned ahi[4], alo[4];
            {
                unsigned addr = smem_u32 + OFF_THI + ((tw0 + rL) * PAD + h0 + cL) * 2;
                ldsm_x4(addr, ahi[0], ahi[1], ahi[2], ahi[3]);
                addr = smem_u32 + OFF_TLO + ((tw0 + rL) * PAD + h0 + cL) * 2;
                ldsm_x4(addr, alo[0], alo[1], alo[2], alo[3]);
            }
            #pragma unroll
            for (int jp = 0; jp < 8; ++jp) {
                const int nA = jp * 16;
                unsigned bh0, bh1, bh2, bh3, bl0, bl1, bl2, bl3;
                unsigned baddr = smem_u32 + OFF_WHI + ((h0 + rL) * PAD + nA + cL) * 2;
                ldsm_x4_t(baddr, bh0, bh1, bh2, bh3);
                baddr = smem_u32 + OFF_WLO + ((h0 + rL) * PAD + nA + cL) * 2;
                ldsm_x4_t(baddr, bl0, bl1, bl2, bl3);
                mma16816(acc[2 * jp],     ahi, bh0, bh1);
                mma16816(acc[2 * jp],     ahi, bl0, bl1);
                mma16816(acc[2 * jp],     alo, bh0, bh1);
                mma16816(acc[2 * jp + 1], ahi, bh2, bh3);
                mma16816(acc[2 * jp + 1], ahi, bl2, bl3);
                mma16816(acc[2 * jp + 1], alo, bh2, bh3);
            }
        }

        // Epilogue: + A + C, exact gelu, dot W2, quad-reduce, softsign, store
        const int ta = tw0 + (lane >> 2);       // local t row (first)
        const int tb = ta + 8;                  // local t row (second)
        const int kb = (lane & 3) * 2;          // col base within n8 tile
        const float2* Ca = (const float2*)(g_C + (gt0 + ta) * H);
        const float2* Cb = (const float2*)(g_C + (gt0 + tb) * H);
        float pa = 0.f, pb = 0.f;
        #pragma unroll
        for (int j = 0; j < 16; ++j) {
            const int k = 8 * j + kb;
            const float2 ca = Ca[k >> 1];
            const float2 cb = Cb[k >> 1];
            const float a0 = As[k], a1 = As[k + 1];
            const float w0 = w2s[k], w1 = w2s[k + 1];
            float h00 = acc[j][0] + a0 + ca.x;
            float h01 = acc[j][1] + a1 + ca.y;
            float h10 = acc[j][2] + a0 + cb.x;
            float h11 = acc[j][3] + a1 + cb.y;
            float g00 = 0.5f * h00 * (1.0f + erff(h00 * 0.7071067811865476f));
            float g01 = 0.5f * h01 * (1.0f + erff(h01 * 0.7071067811865476f));
            float g10 = 0.5f * h10 * (1.0f + erff(h10 * 0.7071067811865476f));
            float g11 = 0.5f * h11 * (1.0f + erff(h11 * 0.7071067811865476f));
            pa = fmaf(g00, w0, pa); pa = fmaf(g01, w1, pa);
            pb = fmaf(g10, w0, pb); pb = fmaf(g11, w1, pb);
        }
        pa += __shfl_xor_sync(0xffffffffu, pa, 1);
        pa += __shfl_xor_sync(0xffffffffu, pa, 2);
        pb += __shfl_xor_sync(0xffffffffu, pb, 1);
        pb += __shfl_xor_sync(0xffffffffu, pb, 2);
        if ((lane & 3) == 0) {
            const int t_out = tt * 128;
            float sa = pa + b2v;
            float sb = pb + b2v;
            out[bs * T + t_out + ta] = (sa / (1.0f + fabsf(sa))) * mval;
            out[bs * T + t_out + tb] = (sb / (1.0f + fabsf(sb))) * mval;
        }
    }
}

// ---------------------------------------------------------------------------
extern "C" void kernel_launch(void* const* d_in, const int* in_sizes, int n_in,
                              void* d_out, int out_size)
{
    const float* sv   = (const float*)d_in[0];
    const float* tv   = (const float*)d_in[1];
    const int*   mask = (const int*)d_in[2];
    const float* sng  = (const float*)d_in[3];
    const float* snb  = (const float*)d_in[4];
    const float* tng  = (const float*)d_in[5];
    const float* tnb  = (const float*)d_in[6];
    const float* Wsu  = (const float*)d_in[7];
    const float* bsu  = (const float*)d_in[8];
    const float* Wtp  = (const float*)d_in[9];
    const float* btp  = (const float*)d_in[10];
    const float* W1   = (const float*)d_in[11];
    const float* b1   = (const float*)d_in[12];
    const float* W2   = (const float*)d_in[13];
    const float* b2   = (const float*)d_in[14];
    float* out = (float*)d_out;

    norm_proj_kernel<<<BS + BT, 256>>>(sv, tv, sng, snb, tng, tnb,
                                       Wsu, bsu, Wtp, btp, W1, b1);

    cudaFuncSetAttribute(edge_main_kernel,
                         cudaFuncAttributeMaxDynamicSharedMemorySize, SMEM_BYTES);
    edge_main_kernel<<<BS, 256, SMEM_BYTES>>>(W1, W2, b2, mask, out);
}

// round 5
// speedup vs baseline: 2.6087x; 1.0122x over previous
#include <cuda_runtime.h>
#include <cuda_bf16.h>

// Shapes (fixed per reference setup_inputs)
#define B 2
#define S 512
#define T 512
#define D 256
#define H 128
#define BS (B*S)        // 1024
#define BT (B*T)        // 1024

#define PAD 136         // padded row stride (elems) for conflict-free ldmatrix

// Scratch (device globals; no allocation allowed)
__device__ float g_src[BS * H];            // LN(source) @ W_su + b_su (fp32)
__device__ float g_A  [BS * H];            // g_src @ W1_s + b1
__device__ float g_C  [BT * H];            // g_tgt @ W1_t
__device__ __nv_bfloat16 g_thi[BT * H];    // bf16 hi of target proj
__device__ __nv_bfloat16 g_tlo[BT * H];    // bf16 lo (residual)

// ---------------------------------------------------------------------------
// Stage 1: per-row layernorm + projection + W1_s / W1_t projection.
// One CTA per row (2048 rows total), 256 threads.
// ---------------------------------------------------------------------------
__global__ __launch_bounds__(256) void norm_proj_kernel(
    const float* __restrict__ sv, const float* __restrict__ tv,
    const float* __restrict__ sng, const float* __restrict__ snb,
    const float* __restrict__ tng, const float* __restrict__ tnb,
    const float* __restrict__ Wsu, const float* __restrict__ bsu,
    const float* __restrict__ Wtp, const float* __restrict__ btp,
    const float* __restrict__ W1,  const float* __restrict__ b1)
{
    __shared__ float xn[D];
    __shared__ float pr[H];
    __shared__ float r1[8], r2[8];

    const int r = blockIdx.x;
    const bool is_src = (r < BS);
    const int row = is_src ? r : r - BS;
    const int tid = threadIdx.x;

    const float* x    = (is_src ? sv : tv) + row * D;
    const float* gv   = is_src ? sng : tng;
    const float* bv   = is_src ? snb : tnb;
    const float* W    = is_src ? Wsu : Wtp;
    const float* bias = is_src ? bsu : btp;

    float v = x[tid];
    float s1 = v, s2 = v * v;
    #pragma unroll
    for (int m = 16; m; m >>= 1) {
        s1 += __shfl_xor_sync(0xffffffffu, s1, m);
        s2 += __shfl_xor_sync(0xffffffffu, s2, m);
    }
    if ((tid & 31) == 0) { r1[tid >> 5] = s1; r2[tid >> 5] = s2; }
    __syncthreads();
    float t1 = 0.f, t2 = 0.f;
    #pragma unroll
    for (int i = 0; i < 8; ++i) { t1 += r1[i]; t2 += r2[i]; }
    const float mean = t1 * (1.0f / D);
    const float var  = t2 * (1.0f / D) - mean * mean;
    const float rs   = rsqrtf(var + 1e-5f);
    xn[tid] = (v - mean) * rs * gv[tid] + bv[tid];
    __syncthreads();

    if (tid < H) {
        float a0 = 0.f, a1 = 0.f, a2 = 0.f, a3 = 0.f;
        #pragma unroll 4
        for (int d = 0; d < D; d += 4) {
            a0 = fmaf(xn[d + 0], W[(d + 0) * H + tid], a0);
            a1 = fmaf(xn[d + 1], W[(d + 1) * H + tid], a1);
            a2 = fmaf(xn[d + 2], W[(d + 2) * H + tid], a2);
            a3 = fmaf(xn[d + 3], W[(d + 3) * H + tid], a3);
        }
        float p = (a0 + a1) + (a2 + a3) + bias[tid];
        pr[tid] = p;
        if (is_src) {
            g_src[row * H + tid] = p;
        } else {
            __nv_bfloat16 hi = __float2bfloat16(p);
            g_thi[row * H + tid] = hi;
            g_tlo[row * H + tid] = __float2bfloat16(p - __bfloat162float(hi));
        }
    }
    __syncthreads();

    if (tid < H) {
        const float* Wr = W1 + (is_src ? 0 : H * H);
        float a0 = 0.f, a1 = 0.f, a2 = 0.f, a3 = 0.f;
        #pragma unroll 4
        for (int h = 0; h < H; h += 4) {
            a0 = fmaf(pr[h + 0], Wr[(h + 0) * H + tid], a0);
            a1 = fmaf(pr[h + 1], Wr[(h + 1) * H + tid], a1);
            a2 = fmaf(pr[h + 2], Wr[(h + 2) * H + tid], a2);
            a3 = fmaf(pr[h + 3], Wr[(h + 3) * H + tid], a3);
        }
        float p = (a0 + a1) + (a2 + a3) + (is_src ? b1[tid] : 0.0f);
        (is_src ? g_A : g_C)[row * H + tid] = p;
    }
}

// ---------------------------------------------------------------------------
// Stage 2: tensor-core fused kernel. One CTA per (b, s). 512 threads, 16 warps.
// Warp tile: 16t x 64k (k split across warp pairs).
// ---------------------------------------------------------------------------
__device__ __forceinline__ void ldsm_x4(unsigned a, unsigned &r0, unsigned &r1,
                                        unsigned &r2, unsigned &r3) {
    asm volatile("ldmatrix.sync.aligned.m8n8.x4.shared.b16 {%0,%1,%2,%3}, [%4];"
        : "=r"(r0), "=r"(r1), "=r"(r2), "=r"(r3) : "r"(a));
}
__device__ __forceinline__ void ldsm_x4_t(unsigned a, unsigned &r0, unsigned &r1,
                                          unsigned &r2, unsigned &r3) {
    asm volatile("ldmatrix.sync.aligned.m8n8.x4.trans.shared.b16 {%0,%1,%2,%3}, [%4];"
        : "=r"(r0), "=r"(r1), "=r"(r2), "=r"(r3) : "r"(a));
}
__device__ __forceinline__ void mma16816(float* c, const unsigned* a,
                                         unsigned b0, unsigned b1) {
    asm volatile("mma.sync.aligned.m16n8k16.row.col.f32.bf16.bf16.f32 "
        "{%0,%1,%2,%3}, {%4,%5,%6,%7}, {%8,%9}, {%0,%1,%2,%3};"
        : "+f"(c[0]), "+f"(c[1]), "+f"(c[2]), "+f"(c[3])
        : "r"(a[0]), "r"(a[1]), "r"(a[2]), "r"(a[3]), "r"(b0), "r"(b1));
}

// smem byte offsets
#define OFF_WHI 0
#define OFF_WLO (OFF_WHI + H*PAD*2)
#define OFF_THI (OFF_WLO + H*PAD*2)
#define OFF_TLO (OFF_THI + H*PAD*2)
#define OFF_SRC (OFF_TLO + H*PAD*2)
#define OFF_AS  (OFF_SRC + H*4)
#define OFF_W2  (OFF_AS  + H*4)
#define OFF_PS  (OFF_W2  + H*4)
#define SMEM_BYTES (OFF_PS + 128*2*4)

#define NTHR 512

extern __shared__ char smem_raw[];

__global__ __launch_bounds__(NTHR, 1) void edge_main_kernel(
    const float* __restrict__ W1, const float* __restrict__ W2,
    const float* __restrict__ b2p, const int* __restrict__ mask,
    float* __restrict__ out)
{
    __nv_bfloat16* Whi = (__nv_bfloat16*)(smem_raw + OFF_WHI);
    __nv_bfloat16* Wlo = (__nv_bfloat16*)(smem_raw + OFF_WLO);
    float* ssrc = (float*)(smem_raw + OFF_SRC);
    float* As   = (float*)(smem_raw + OFF_AS);
    float* w2s  = (float*)(smem_raw + OFF_W2);
    float* psum = (float*)(smem_raw + OFF_PS);     // [128][2]

    unsigned smem_u32;
    asm("{ .reg .u64 t; cvta.to.shared.u64 t, %1; cvt.u32.u64 %0, t; }"
        : "=r"(smem_u32) : "l"(smem_raw));

    const int bs  = blockIdx.x;
    const int b   = bs >> 9;
    const int tid = threadIdx.x;
    const int wid = tid >> 5;
    const int lane = tid & 31;

    if (tid < H) {
        ssrc[tid] = g_src[bs * H + tid];
        As[tid]   = g_A[bs * H + tid];
        w2s[tid]  = W2[tid];
    }
    __syncthreads();

    // Prologue: Whi/Wlo[h][k] = split( src[h] * W1_st[h][k] ), padded stride
    {
        const float4* Wst4 = (const float4*)(W1 + 2 * H * H);
        for (int i = tid; i < (H * H) / 4; i += NTHR) {
            const int h = i >> 5;
            const int c = (i & 31) * 4;
            const float sc = ssrc[h];
            float4 w = Wst4[i];
            float v0 = w.x * sc, v1 = w.y * sc, v2 = w.z * sc, v3 = w.w * sc;
            __nv_bfloat16 h0 = __float2bfloat16(v0);
            __nv_bfloat16 h1 = __float2bfloat16(v1);
            __nv_bfloat16 h2 = __float2bfloat16(v2);
            __nv_bfloat16 h3 = __float2bfloat16(v3);
            Whi[h * PAD + c + 0] = h0;  Whi[h * PAD + c + 1] = h1;
            Whi[h * PAD + c + 2] = h2;  Whi[h * PAD + c + 3] = h3;
            Wlo[h * PAD + c + 0] = __float2bfloat16(v0 - __bfloat162float(h0));
            Wlo[h * PAD + c + 1] = __float2bfloat16(v1 - __bfloat162float(h1));
            Wlo[h * PAD + c + 2] = __float2bfloat16(v2 - __bfloat162float(h2));
            Wlo[h * PAD + c + 3] = __float2bfloat16(v3 - __bfloat162float(h3));
        }
    }

    const float b2v  = b2p[0];
    const float mval = mask[bs] ? 1.0f : 0.0f;

    // Warp tiling: 8 t-groups x 2 k-halves
    const int tw0 = (wid >> 1) * 16;    // t base (0..112)
    const int kh  = (wid & 1) * 64;     // k half base (0 or 64)
    const int rL = lane & 15;
    const int cL = (lane >> 4) << 3;

    for (int tt = 0; tt < T / 128; ++tt) {
        const int gt0 = (b << 9) + tt * 128;
        __syncthreads();

        // Fill Thi/Tlo[t][h] (16B chunks, padded stride)
        {
            const uint4* shi = (const uint4*)(g_thi + gt0 * H);
            const uint4* slo = (const uint4*)(g_tlo + gt0 * H);
            for (int i = tid; i < 128 * 16; i += NTHR) {
                const int row = i >> 4;
                const int c8  = i & 15;
                *(uint4*)(smem_raw + OFF_THI + (row * PAD + c8 * 8) * 2) = shi[row * 16 + c8];
                *(uint4*)(smem_raw + OFF_TLO + (row * PAD + c8 * 8) * 2) = slo[row * 16 + c8];
            }
        }
        __syncthreads();

        // Mainloop: 16t x 64k per warp, K=128 in 8 steps, 3 bf16 passes
        float acc[8][4];
        #pragma unroll
        for (int i = 0; i < 8; ++i)
            #pragma unroll
            for (int j = 0; j < 4; ++j) acc[i][j] = 0.f;

        #pragma unroll
        for (int step = 0; step < 8; ++step) {
            const int h0 = step * 16;
            unsigned ahi[4], alo[4];
            {
                unsigned addr = smem_u32 + OFF_THI + ((tw0 + rL) * PAD + h0 + cL) * 2;
                ldsm_x4(addr, ahi[0], ahi[1], ahi[2], ahi[3]);
                addr = smem_u32 + OFF_TLO + ((tw0 + rL) * PAD + h0 + cL) * 2;
                ldsm_x4(addr, alo[0], alo[1], alo[2], alo[3]);
            }
            #pragma unroll
            for (int jp = 0; jp < 4; ++jp) {
                const int nA = kh + jp * 16;
                unsigned bh0, bh1, bh2, bh3, bl0, bl1, bl2, bl3;
                unsigned baddr = smem_u32 + OFF_WHI + ((h0 + rL) * PAD + nA + cL) * 2;
                ldsm_x4_t(baddr, bh0, bh1, bh2, bh3);
                baddr = smem_u32 + OFF_WLO + ((h0 + rL) * PAD + nA + cL) * 2;
                ldsm_x4_t(baddr, bl0, bl1, bl2, bl3);
                mma16816(acc[2 * jp],     ahi, bh0, bh1);
                mma16816(acc[2 * jp],     ahi, bl0, bl1);
                mma16816(acc[2 * jp],     alo, bh0, bh1);
                mma16816(acc[2 * jp + 1], ahi, bh2, bh3);
                mma16816(acc[2 * jp + 1], ahi, bl2, bl3);
                mma16816(acc[2 * jp + 1], alo, bh2, bh3);
            }
        }

        // Epilogue: + A + C, exact gelu, dot W2 over this warp's 64 k,
        // quad-reduce, cross-warp combine in smem, softsign, store.
        const int ta = tw0 + (lane >> 2);
        const int tb = ta + 8;
        const int kb = (lane & 3) * 2;
        const float2* Ca = (const float2*)(g_C + (gt0 + ta) * H);
        const float2* Cb = (const float2*)(g_C + (gt0 + tb) * H);
        float pa = 0.f, pb = 0.f;
        #pragma unroll
        for (int j = 0; j < 8; ++j) {
            const int k = kh + 8 * j + kb;
            const float2 ca = Ca[k >> 1];
            const float2 cb = Cb[k >> 1];
            const float a0 = As[k], a1 = As[k + 1];
            const float w0 = w2s[k], w1 = w2s[k + 1];
            float h00 = acc[j][0] + a0 + ca.x;
            float h01 = acc[j][1] + a1 + ca.y;
            float h10 = acc[j][2] + a0 + cb.x;
            float h11 = acc[j][3] + a1 + cb.y;
            float g00 = 0.5f * h00 * (1.0f + erff(h00 * 0.7071067811865476f));
            float g01 = 0.5f * h01 * (1.0f + erff(h01 * 0.7071067811865476f));
            float g10 = 0.5f * h10 * (1.0f + erff(h10 * 0.7071067811865476f));
            float g11 = 0.5f * h11 * (1.0f + erff(h11 * 0.7071067811865476f));
            pa = fmaf(g00, w0, pa); pa = fmaf(g01, w1, pa);
            pb = fmaf(g10, w0, pb); pb = fmaf(g11, w1, pb);
        }
        pa += __shfl_xor_sync(0xffffffffu, pa, 1);
        pa += __shfl_xor_sync(0xffffffffu, pa, 2);
        pb += __shfl_xor_sync(0xffffffffu, pb, 1);
        pb += __shfl_xor_sync(0xffffffffu, pb, 2);
        if ((lane & 3) == 0) {
            psum[ta * 2 + (wid & 1)] = pa;
            psum[tb * 2 + (wid & 1)] = pb;
        }
        __syncthreads();
        if (tid < 128) {
            const float sc = psum[tid * 2] + psum[tid * 2 + 1] + b2v;
            const float e  = sc / (1.0f + fabsf(sc));
            out[bs * T + tt * 128 + tid] = e * mval;
        }
    }
}

// ---------------------------------------------------------------------------
extern "C" void kernel_launch(void* const* d_in, const int* in_sizes, int n_in,
                              void* d_out, int out_size)
{
    const float* sv   = (const float*)d_in[0];
    const float* tv   = (const float*)d_in[1];
    const int*   mask = (const int*)d_in[2];
    const float* sng  = (const float*)d_in[3];
    const float* snb  = (const float*)d_in[4];
    const float* tng  = (const float*)d_in[5];
    const float* tnb  = (const float*)d_in[6];
    const float* Wsu  = (const float*)d_in[7];
    const float* bsu  = (const float*)d_in[8];
    const float* Wtp  = (const float*)d_in[9];
    const float* btp  = (const float*)d_in[10];
    const float* W1   = (const float*)d_in[11];
    const float* b1   = (const float*)d_in[12];
    const float* W2   = (const float*)d_in[13];
    const float* b2   = (const float*)d_in[14];
    float* out = (float*)d_out;

    norm_proj_kernel<<<BS + BT, 256>>>(sv, tv, sng, snb, tng, tnb,
                                       Wsu, bsu, Wtp, btp, W1, b1);

    cudaFuncSetAttribute(edge_main_kernel,
                         cudaFuncAttributeMaxDynamicSharedMemorySize, SMEM_BYTES);
    edge_main_kernel<<<BS, NTHR, SMEM_BYTES>>>(W1, W2, b2, mask, out);
}

// round 7
// speedup vs baseline: 3.0452x; 1.1673x over previous
#include <cuda_runtime.h>
#include <cuda_fp16.h>
#include <cstdint>

// Shapes (fixed per reference setup_inputs)
#define B 2
#define S 512
#define T 512
#define D 256
#define H 128
#define BS (B*S)        // 1024
#define BT (B*T)        // 1024

#define PAD 136         // padded row stride (elems) for conflict-free ldmatrix

// Scratch (device globals; no allocation allowed)
__device__ float g_src[BS * H];       // LN(source) @ W_su + b_su (fp32)
__device__ float g_A  [BS * H];       // g_src @ W1_s + b1
__device__ float g_C  [BT * H];       // g_tgt @ W1_t
__device__ __half g_th [BT * H];      // fp16 target proj

// ---------------------------------------------------------------------------
// Stage 1: per-row layernorm + projection + W1_s / W1_t projection.
// ---------------------------------------------------------------------------
__global__ __launch_bounds__(256) void norm_proj_kernel(
    const float* __restrict__ sv, const float* __restrict__ tv,
    const float* __restrict__ sng, const float* __restrict__ snb,
    const float* __restrict__ tng, const float* __restrict__ tnb,
    const float* __restrict__ Wsu, const float* __restrict__ bsu,
    const float* __restrict__ Wtp, const float* __restrict__ btp,
    const float* __restrict__ W1,  const float* __restrict__ b1)
{
    __shared__ float xn[D];
    __shared__ float pr[H];
    __shared__ float r1[8], r2[8];

    const int r = blockIdx.x;
    const bool is_src = (r < BS);
    const int row = is_src ? r : r - BS;
    const int tid = threadIdx.x;

    const float* x    = (is_src ? sv : tv) + row * D;
    const float* gv   = is_src ? sng : tng;
    const float* bv   = is_src ? snb : tnb;
    const float* W    = is_src ? Wsu : Wtp;
    const float* bias = is_src ? bsu : btp;

    float v = x[tid];
    float s1 = v, s2 = v * v;
    #pragma unroll
    for (int m = 16; m; m >>= 1) {
        s1 += __shfl_xor_sync(0xffffffffu, s1, m);
        s2 += __shfl_xor_sync(0xffffffffu, s2, m);
    }
    if ((tid & 31) == 0) { r1[tid >> 5] = s1; r2[tid >> 5] = s2; }
    __syncthreads();
    float t1 = 0.f, t2 = 0.f;
    #pragma unroll
    for (int i = 0; i < 8; ++i) { t1 += r1[i]; t2 += r2[i]; }
    const float mean = t1 * (1.0f / D);
    const float var  = t2 * (1.0f / D) - mean * mean;
    const float rs   = rsqrtf(var + 1e-5f);
    xn[tid] = (v - mean) * rs * gv[tid] + bv[tid];
    __syncthreads();

    if (tid < H) {
        float a0 = 0.f, a1 = 0.f, a2 = 0.f, a3 = 0.f;
        #pragma unroll 4
        for (int d = 0; d < D; d += 4) {
            a0 = fmaf(xn[d + 0], W[(d + 0) * H + tid], a0);
            a1 = fmaf(xn[d + 1], W[(d + 1) * H + tid], a1);
            a2 = fmaf(xn[d + 2], W[(d + 2) * H + tid], a2);
            a3 = fmaf(xn[d + 3], W[(d + 3) * H + tid], a3);
        }
        float p = (a0 + a1) + (a2 + a3) + bias[tid];
        pr[tid] = p;
        if (is_src) g_src[row * H + tid] = p;
        else        g_th[row * H + tid]  = __float2half(p);
    }
    __syncthreads();

    if (tid < H) {
        const float* Wr = W1 + (is_src ? 0 : H * H);
        float a0 = 0.f, a1 = 0.f, a2 = 0.f, a3 = 0.f;
        #pragma unroll 4
        for (int h = 0; h < H; h += 4) {
            a0 = fmaf(pr[h + 0], Wr[(h + 0) * H + tid], a0);
            a1 = fmaf(pr[h + 1], Wr[(h + 1) * H + tid], a1);
            a2 = fmaf(pr[h + 2], Wr[(h + 2) * H + tid], a2);
            a3 = fmaf(pr[h + 3], Wr[(h + 3) * H + tid], a3);
        }
        float p = (a0 + a1) + (a2 + a3) + (is_src ? b1[tid] : 0.0f);
        (is_src ? g_A : g_C)[row * H + tid] = p;
    }
}

// ---------------------------------------------------------------------------
// Stage 2: mma.sync fp16 fused kernel. One CTA per (b,s). 512 threads/16 warps.
// Warp tile: 32t x 32k.  hidden = Th @ (Whi + Wlo) exactly (W split in fp16).
// ---------------------------------------------------------------------------
__device__ __forceinline__ void ldsm_x4(unsigned a, unsigned &r0, unsigned &r1,
                                        unsigned &r2, unsigned &r3) {
    asm volatile("ldmatrix.sync.aligned.m8n8.x4.shared.b16 {%0,%1,%2,%3}, [%4];"
        : "=r"(r0), "=r"(r1), "=r"(r2), "=r"(r3) : "r"(a));
}
__device__ __forceinline__ void ldsm_x4_t(unsigned a, unsigned &r0, unsigned &r1,
                                          unsigned &r2, unsigned &r3) {
    asm volatile("ldmatrix.sync.aligned.m8n8.x4.trans.shared.b16 {%0,%1,%2,%3}, [%4];"
        : "=r"(r0), "=r"(r1), "=r"(r2), "=r"(r3) : "r"(a));
}
__device__ __forceinline__ void mma16816(float* c, const unsigned* a,
                                         unsigned b0, unsigned b1) {
    asm volatile("mma.sync.aligned.m16n8k16.row.col.f32.f16.f16.f32 "
        "{%0,%1,%2,%3}, {%4,%5,%6,%7}, {%8,%9}, {%0,%1,%2,%3};"
        : "+f"(c[0]), "+f"(c[1]), "+f"(c[2]), "+f"(c[3])
        : "r"(a[0]), "r"(a[1]), "r"(a[2]), "r"(a[3]), "r"(b0), "r"(b1));
}

// smem byte offsets
#define OFF_WHI 0
#define OFF_WLO (OFF_WHI + H*PAD*2)
#define OFF_TH  (OFF_WLO + H*PAD*2)
#define OFF_SRC (OFF_TH  + H*PAD*2)
#define OFF_AS  (OFF_SRC + H*4)
#define OFF_W2  (OFF_AS  + H*4)
#define OFF_PS  (OFF_W2  + H*4)
#define SMEM_BYTES (OFF_PS + 128*4*4)

#define NTHR 512

extern __shared__ char smem_raw[];

__global__ __launch_bounds__(NTHR, 1) void edge_main_kernel(
    const float* __restrict__ W1, const float* __restrict__ W2,
    const float* __restrict__ b2p, const int* __restrict__ mask,
    float* __restrict__ out)
{
    __half* Whi = (__half*)(smem_raw + OFF_WHI);
    __half* Wlo = (__half*)(smem_raw + OFF_WLO);
    float* ssrc = (float*)(smem_raw + OFF_SRC);
    float* As   = (float*)(smem_raw + OFF_AS);
    float* w2s  = (float*)(smem_raw + OFF_W2);
    float* psum = (float*)(smem_raw + OFF_PS);     // [128][4]

    unsigned smem_u32;
    asm("{ .reg .u64 t; cvta.to.shared.u64 t, %1; cvt.u32.u64 %0, t; }"
        : "=r"(smem_u32) : "l"(smem_raw));

    const int bs  = blockIdx.x;
    const int b   = bs >> 9;
    const int tid = threadIdx.x;
    const int wid = tid >> 5;
    const int lane = tid & 31;

    if (tid < H) {
        ssrc[tid] = g_src[bs * H + tid];
        As[tid]   = g_A[bs * H + tid];
        w2s[tid]  = W2[tid];
    }
    __syncthreads();

    // Prologue: Whi/Wlo[h][k] = fp16 split of ( src[h] * W1_st[h][k] )
    {
        const float4* Wst4 = (const float4*)(W1 + 2 * H * H);
        for (int i = tid; i < (H * H) / 4; i += NTHR) {
            const int h = i >> 5;
            const int c = (i & 31) * 4;
            const float sc = ssrc[h];
            float4 w = Wst4[i];
            float vv[4] = {w.x * sc, w.y * sc, w.z * sc, w.w * sc};
            #pragma unroll
            for (int j = 0; j < 4; ++j) {
                __half hi = __float2half(vv[j]);
                Whi[h * PAD + c + j] = hi;
                Wlo[h * PAD + c + j] = __float2half(vv[j] - __half2float(hi));
            }
        }
    }

    const float b2v  = b2p[0];
    const float mval = mask[bs] ? 1.0f : 0.0f;

    // Warp tiling: 4 t-groups x 4 k-groups of 32x32
    const int tw0 = (wid >> 2) * 32;    // t base
    const int kq  = (wid & 3) * 32;     // k base
    const int rL = lane & 15;
    const int cL = (lane >> 4) << 3;

    for (int tt = 0; tt < T / 128; ++tt) {
        const int gt0 = (b << 9) + tt * 128;
        __syncthreads();

        // Fill Th[t][h] (16B chunks, padded stride)
        {
            const uint4* sth = (const uint4*)(g_th + gt0 * H);
            for (int i = tid; i < 128 * 16; i += NTHR) {
                const int row = i >> 4;
                const int c8  = i & 15;
                *(uint4*)(smem_raw + OFF_TH + (row * PAD + c8 * 8) * 2) = sth[i];
            }
        }
        __syncthreads();

        // Mainloop: 32t x 32k per warp, K=128 in 8 steps, 2 passes (Whi,Wlo)
        float acc[2][4][4];
        #pragma unroll
        for (int f = 0; f < 2; ++f)
            #pragma unroll
            for (int g = 0; g < 4; ++g)
                #pragma unroll
                for (int j = 0; j < 4; ++j) acc[f][g][j] = 0.f;

        #pragma unroll
        for (int step = 0; step < 8; ++step) {
            const int h0 = step * 16;
            unsigned ath[2][4];
            #pragma unroll
            for (int f = 0; f < 2; ++f) {
                unsigned addr = smem_u32 + OFF_TH
                              + ((tw0 + f * 16 + rL) * PAD + h0 + cL) * 2;
                ldsm_x4(addr, ath[f][0], ath[f][1], ath[f][2], ath[f][3]);
            }
            #pragma unroll
            for (int g = 0; g < 2; ++g) {
                const int nA = kq + g * 16;
                unsigned bh0, bh1, bh2, bh3, bl0, bl1, bl2, bl3;
                unsigned baddr = smem_u32 + OFF_WHI + ((h0 + rL) * PAD + nA + cL) * 2;
                ldsm_x4_t(baddr, bh0, bh1, bh2, bh3);
                baddr = smem_u32 + OFF_WLO + ((h0 + rL) * PAD + nA + cL) * 2;
                ldsm_x4_t(baddr, bl0, bl1, bl2, bl3);
                #pragma unroll
                for (int f = 0; f < 2; ++f) {
                    mma16816(acc[f][2 * g],     ath[f], bh0, bh1);
                    mma16816(acc[f][2 * g],     ath[f], bl0, bl1);
                    mma16816(acc[f][2 * g + 1], ath[f], bh2, bh3);
                    mma16816(acc[f][2 * g + 1], ath[f], bl2, bl3);
                }
            }
        }

        // Epilogue: + A + C, exact gelu, dot W2 over this warp's 32 k,
        // quad-reduce, psum combine, softsign, store.
        #pragma unroll
        for (int f = 0; f < 2; ++f) {
            #pragma unroll
            for (int hf = 0; hf < 2; ++hf) {
                const int t = tw0 + f * 16 + (lane >> 2) + hf * 8;
                const float2* Cr = (const float2*)(g_C + (gt0 + t) * H);
                float pt = 0.f;
                #pragma unroll
                for (int g = 0; g < 4; ++g) {
                    const int k = kq + g * 8 + (lane & 3) * 2;
                    const float2 cc = Cr[k >> 1];
                    float h0v = acc[f][g][hf * 2 + 0] + As[k]     + cc.x;
                    float h1v = acc[f][g][hf * 2 + 1] + As[k + 1] + cc.y;
                    float g0 = 0.5f * h0v * (1.0f + erff(h0v * 0.7071067811865476f));
                    float g1 = 0.5f * h1v * (1.0f + erff(h1v * 0.7071067811865476f));
                    pt = fmaf(g0, w2s[k], pt);
                    pt = fmaf(g1, w2s[k + 1], pt);
                }
                pt += __shfl_xor_sync(0xffffffffu, pt, 1);
                pt += __shfl_xor_sync(0xffffffffu, pt, 2);
                if ((lane & 3) == 0)
                    psum[t * 4 + (wid & 3)] = pt;
            }
        }
        __syncthreads();

        if (tid < 128) {
            const float sc = psum[tid * 4] + psum[tid * 4 + 1]
                           + psum[tid * 4 + 2] + psum[tid * 4 + 3] + b2v;
            const float e  = sc / (1.0f + fabsf(sc));
            out[bs * T + tt * 128 + tid] = e * mval;
        }
    }
}

// ---------------------------------------------------------------------------
extern "C" void kernel_launch(void* const* d_in, const int* in_sizes, int n_in,
                              void* d_out, int out_size)
{
    const float* sv   = (const float*)d_in[0];
    const float* tv   = (const float*)d_in[1];
    const int*   mask = (const int*)d_in[2];
    const float* sng  = (const float*)d_in[3];
    const float* snb  = (const float*)d_in[4];
    const float* tng  = (const float*)d_in[5];
    const float* tnb  = (const float*)d_in[6];
    const float* Wsu  = (const float*)d_in[7];
    const float* bsu  = (const float*)d_in[8];
    const float* Wtp  = (const float*)d_in[9];
    const float* btp  = (const float*)d_in[10];
    const float* W1   = (const float*)d_in[11];
    const float* b1   = (const float*)d_in[12];
    const float* W2   = (const float*)d_in[13];
    const float* b2   = (const float*)d_in[14];
    float* out = (float*)d_out;

    norm_proj_kernel<<<BS + BT, 256>>>(sv, tv, sng, snb, tng, tnb,
                                       Wsu, bsu, Wtp, btp, W1, b1);

    cudaFuncSetAttribute(edge_main_kernel,
                         cudaFuncAttributeMaxDynamicSharedMemorySize, SMEM_BYTES);
    edge_main_kernel<<<BS, NTHR, SMEM_BYTES>>>(W1, W2, b2, mask, out);
}

// round 8
// speedup vs baseline: 3.4501x; 1.1330x over previous
#include <cuda_runtime.h>
#include <cuda_fp16.h>
#include <cstdint>

// Shapes (fixed per reference setup_inputs)
#define B 2
#define S 512
#define T 512
#define D 256
#define H 128
#define BS (B*S)        // 1024
#define BT (B*T)        // 1024

#define PAD 136         // padded row stride (elems) for conflict-free ldmatrix

// Scratch (device globals; no allocation allowed)
__device__ float g_src[BS * H];       // LN(source) @ W_su + b_su (fp32)
__device__ float g_A  [BS * H];       // g_src @ W1_s + b1
__device__ float g_C  [BT * H];       // g_tgt @ W1_t
__device__ __half g_th [BT * H];      // fp16 target proj

// ---------------------------------------------------------------------------
// Stage 1: per-row layernorm + projection + W1_s / W1_t projection.
// ---------------------------------------------------------------------------
__global__ __launch_bounds__(256) void norm_proj_kernel(
    const float* __restrict__ sv, const float* __restrict__ tv,
    const float* __restrict__ sng, const float* __restrict__ snb,
    const float* __restrict__ tng, const float* __restrict__ tnb,
    const float* __restrict__ Wsu, const float* __restrict__ bsu,
    const float* __restrict__ Wtp, const float* __restrict__ btp,
    const float* __restrict__ W1,  const float* __restrict__ b1)
{
    __shared__ float xn[D];
    __shared__ float pr[H];
    __shared__ float r1[8], r2[8];

    const int r = blockIdx.x;
    const bool is_src = (r < BS);
    const int row = is_src ? r : r - BS;
    const int tid = threadIdx.x;

    const float* x    = (is_src ? sv : tv) + row * D;
    const float* gv   = is_src ? sng : tng;
    const float* bv   = is_src ? snb : tnb;
    const float* W    = is_src ? Wsu : Wtp;
    const float* bias = is_src ? bsu : btp;

    float v = x[tid];
    float s1 = v, s2 = v * v;
    #pragma unroll
    for (int m = 16; m; m >>= 1) {
        s1 += __shfl_xor_sync(0xffffffffu, s1, m);
        s2 += __shfl_xor_sync(0xffffffffu, s2, m);
    }
    if ((tid & 31) == 0) { r1[tid >> 5] = s1; r2[tid >> 5] = s2; }
    __syncthreads();
    float t1 = 0.f, t2 = 0.f;
    #pragma unroll
    for (int i = 0; i < 8; ++i) { t1 += r1[i]; t2 += r2[i]; }
    const float mean = t1 * (1.0f / D);
    const float var  = t2 * (1.0f / D) - mean * mean;
    const float rs   = rsqrtf(var + 1e-5f);
    xn[tid] = (v - mean) * rs * gv[tid] + bv[tid];
    __syncthreads();

    if (tid < H) {
        float a0 = 0.f, a1 = 0.f, a2 = 0.f, a3 = 0.f;
        #pragma unroll 4
        for (int d = 0; d < D; d += 4) {
            a0 = fmaf(xn[d + 0], W[(d + 0) * H + tid], a0);
            a1 = fmaf(xn[d + 1], W[(d + 1) * H + tid], a1);
            a2 = fmaf(xn[d + 2], W[(d + 2) * H + tid], a2);
            a3 = fmaf(xn[d + 3], W[(d + 3) * H + tid], a3);
        }
        float p = (a0 + a1) + (a2 + a3) + bias[tid];
        pr[tid] = p;
        if (is_src) g_src[row * H + tid] = p;
        else        g_th[row * H + tid]  = __float2half(p);
    }
    __syncthreads();

    if (tid < H) {
        const float* Wr = W1 + (is_src ? 0 : H * H);
        float a0 = 0.f, a1 = 0.f, a2 = 0.f, a3 = 0.f;
        #pragma unroll 4
        for (int h = 0; h < H; h += 4) {
            a0 = fmaf(pr[h + 0], Wr[(h + 0) * H + tid], a0);
            a1 = fmaf(pr[h + 1], Wr[(h + 1) * H + tid], a1);
            a2 = fmaf(pr[h + 2], Wr[(h + 2) * H + tid], a2);
            a3 = fmaf(pr[h + 3], Wr[(h + 3) * H + tid], a3);
        }
        float p = (a0 + a1) + (a2 + a3) + (is_src ? b1[tid] : 0.0f);
        (is_src ? g_A : g_C)[row * H + tid] = p;
    }
}

// ---------------------------------------------------------------------------
// Stage 2: mma.sync fp16 fused kernel (single pass). One CTA per (b,s).
// 512 threads / 16 warps. Warp tile: 32t x 32k.
// ---------------------------------------------------------------------------
__device__ __forceinline__ void ldsm_x4(unsigned a, unsigned &r0, unsigned &r1,
                                        unsigned &r2, unsigned &r3) {
    asm volatile("ldmatrix.sync.aligned.m8n8.x4.shared.b16 {%0,%1,%2,%3}, [%4];"
        : "=r"(r0), "=r"(r1), "=r"(r2), "=r"(r3) : "r"(a));
}
__device__ __forceinline__ void ldsm_x4_t(unsigned a, unsigned &r0, unsigned &r1,
                                          unsigned &r2, unsigned &r3) {
    asm volatile("ldmatrix.sync.aligned.m8n8.x4.trans.shared.b16 {%0,%1,%2,%3}, [%4];"
        : "=r"(r0), "=r"(r1), "=r"(r2), "=r"(r3) : "r"(a));
}
__device__ __forceinline__ void mma16816(float* c, const unsigned* a,
                                         unsigned b0, unsigned b1) {
    asm volatile("mma.sync.aligned.m16n8k16.row.col.f32.f16.f16.f32 "
        "{%0,%1,%2,%3}, {%4,%5,%6,%7}, {%8,%9}, {%0,%1,%2,%3};"
        : "+f"(c[0]), "+f"(c[1]), "+f"(c[2]), "+f"(c[3])
        : "r"(a[0]), "r"(a[1]), "r"(a[2]), "r"(a[3]), "r"(b0), "r"(b1));
}

// smem byte offsets
#define OFF_WHI 0
#define OFF_TH  (OFF_WHI + H*PAD*2)
#define OFF_SRC (OFF_TH  + H*PAD*2)
#define OFF_AS  (OFF_SRC + H*4)
#define OFF_W2  (OFF_AS  + H*4)
#define OFF_PS  (OFF_W2  + H*4)
#define SMEM_BYTES (OFF_PS + 128*4*4)

#define NTHR 512

extern __shared__ char smem_raw[];

__global__ __launch_bounds__(NTHR, 1) void edge_main_kernel(
    const float* __restrict__ W1, const float* __restrict__ W2,
    const float* __restrict__ b2p, const int* __restrict__ mask,
    float* __restrict__ out)
{
    __half* Whi = (__half*)(smem_raw + OFF_WHI);
    float* ssrc = (float*)(smem_raw + OFF_SRC);
    float* As   = (float*)(smem_raw + OFF_AS);
    float* w2s  = (float*)(smem_raw + OFF_W2);
    float* psum = (float*)(smem_raw + OFF_PS);     // [128][4]

    unsigned smem_u32;
    asm("{ .reg .u64 t; cvta.to.shared.u64 t, %1; cvt.u32.u64 %0, t; }"
        : "=r"(smem_u32) : "l"(smem_raw));

    const int bs  = blockIdx.x;
    const int b   = bs >> 9;
    const int tid = threadIdx.x;
    const int wid = tid >> 5;
    const int lane = tid & 31;

    if (tid < H) {
        ssrc[tid] = g_src[bs * H + tid];
        As[tid]   = g_A[bs * H + tid];
        w2s[tid]  = W2[tid];
    }
    __syncthreads();

    // Prologue: Whi[h][k] = fp16( src[h] * W1_st[h][k] )
    {
        const float4* Wst4 = (const float4*)(W1 + 2 * H * H);
        for (int i = tid; i < (H * H) / 4; i += NTHR) {
            const int h = i >> 5;
            const int c = (i & 31) * 4;
            const float sc = ssrc[h];
            float4 w = Wst4[i];
            Whi[h * PAD + c + 0] = __float2half(w.x * sc);
            Whi[h * PAD + c + 1] = __float2half(w.y * sc);
            Whi[h * PAD + c + 2] = __float2half(w.z * sc);
            Whi[h * PAD + c + 3] = __float2half(w.w * sc);
        }
    }

    const float b2v  = b2p[0];
    const float mval = mask[bs] ? 1.0f : 0.0f;

    // Warp tiling: 4 t-groups x 4 k-groups of 32x32
    const int tw0 = (wid >> 2) * 32;    // t base
    const int kq  = (wid & 3) * 32;     // k base
    const int rL = lane & 15;
    const int cL = (lane >> 4) << 3;

    for (int tt = 0; tt < T / 128; ++tt) {
        const int gt0 = (b << 9) + tt * 128;
        __syncthreads();

        // Fill Th[t][h] (16B chunks, padded stride)
        {
            const uint4* sth = (const uint4*)(g_th + gt0 * H);
            for (int i = tid; i < 128 * 16; i += NTHR) {
                const int row = i >> 4;
                const int c8  = i & 15;
                *(uint4*)(smem_raw + OFF_TH + (row * PAD + c8 * 8) * 2) = sth[i];
            }
        }
        __syncthreads();

        // Mainloop: 32t x 32k per warp, K=128 in 8 steps, single fp16 pass
        float acc[2][4][4];
        #pragma unroll
        for (int f = 0; f < 2; ++f)
            #pragma unroll
            for (int g = 0; g < 4; ++g)
                #pragma unroll
                for (int j = 0; j < 4; ++j) acc[f][g][j] = 0.f;

        #pragma unroll
        for (int step = 0; step < 8; ++step) {
            const int h0 = step * 16;
            unsigned ath[2][4];
            #pragma unroll
            for (int f = 0; f < 2; ++f) {
                unsigned addr = smem_u32 + OFF_TH
                              + ((tw0 + f * 16 + rL) * PAD + h0 + cL) * 2;
                ldsm_x4(addr, ath[f][0], ath[f][1], ath[f][2], ath[f][3]);
            }
            #pragma unroll
            for (int g = 0; g < 2; ++g) {
                const int nA = kq + g * 16;
                unsigned bh0, bh1, bh2, bh3;
                unsigned baddr = smem_u32 + OFF_WHI + ((h0 + rL) * PAD + nA + cL) * 2;
                ldsm_x4_t(baddr, bh0, bh1, bh2, bh3);
                #pragma unroll
                for (int f = 0; f < 2; ++f) {
                    mma16816(acc[f][2 * g],     ath[f], bh0, bh1);
                    mma16816(acc[f][2 * g + 1], ath[f], bh2, bh3);
                }
            }
        }

        // Epilogue: + A + C, exact gelu, dot W2 over this warp's 32 k,
        // quad-reduce, psum combine, softsign, store.
        #pragma unroll
        for (int f = 0; f < 2; ++f) {
            #pragma unroll
            for (int hf = 0; hf < 2; ++hf) {
                const int t = tw0 + f * 16 + (lane >> 2) + hf * 8;
                const float2* Cr = (const float2*)(g_C + (gt0 + t) * H);
                float pt = 0.f;
                #pragma unroll
                for (int g = 0; g < 4; ++g) {
                    const int k = kq + g * 8 + (lane & 3) * 2;
                    const float2 cc = Cr[k >> 1];
                    float h0v = acc[f][g][hf * 2 + 0] + As[k]     + cc.x;
                    float h1v = acc[f][g][hf * 2 + 1] + As[k + 1] + cc.y;
                    float g0 = 0.5f * h0v * (1.0f + erff(h0v * 0.7071067811865476f));
                    float g1 = 0.5f * h1v * (1.0f + erff(h1v * 0.7071067811865476f));
                    pt = fmaf(g0, w2s[k], pt);
                    pt = fmaf(g1, w2s[k + 1], pt);
                }
                pt += __shfl_xor_sync(0xffffffffu, pt, 1);
                pt += __shfl_xor_sync(0xffffffffu, pt, 2);
                if ((lane & 3) == 0)
                    psum[t * 4 + (wid & 3)] = pt;
            }
        }
        __syncthreads();

        if (tid < 128) {
            const float sc = psum[tid * 4] + psum[tid * 4 + 1]
                           + psum[tid * 4 + 2] + psum[tid * 4 + 3] + b2v;
            const float e  = sc / (1.0f + fabsf(sc));
            out[bs * T + tt * 128 + tid] = e * mval;
        }
    }
}

// ---------------------------------------------------------------------------
extern "C" void kernel_launch(void* const* d_in, const int* in_sizes, int n_in,
                              void* d_out, int out_size)
{
    const float* sv   = (const float*)d_in[0];
    const float* tv   = (const float*)d_in[1];
    const int*   mask = (const int*)d_in[2];
    const float* sng  = (const float*)d_in[3];
    const float* snb  = (const float*)d_in[4];
    const float* tng  = (const float*)d_in[5];
    const float* tnb  = (const float*)d_in[6];
    const float* Wsu  = (const float*)d_in[7];
    const float* bsu  = (const float*)d_in[8];
    const float* Wtp  = (const float*)d_in[9];
    const float* btp  = (const float*)d_in[10];
    const float* W1   = (const float*)d_in[11];
    const float* b1   = (const float*)d_in[12];
    const float* W2   = (const float*)d_in[13];
    const float* b2   = (const float*)d_in[14];
    float* out = (float*)d_out;

    norm_proj_kernel<<<BS + BT, 256>>>(sv, tv, sng, snb, tng, tnb,
                                       Wsu, bsu, Wtp, btp, W1, b1);

    cudaFuncSetAttribute(edge_main_kernel,
                         cudaFuncAttributeMaxDynamicSharedMemorySize, SMEM_BYTES);
    edge_main_kernel<<<BS, NTHR, SMEM_BYTES>>>(W1, W2, b2, mask, out);
}

// round 9
// speedup vs baseline: 3.9587x; 1.1474x over previous
#include <cuda_runtime.h>
#include <cuda_fp16.h>
#include <cstdint>

// Shapes (fixed per reference setup_inputs)
#define B 2
#define S 512
#define T 512
#define D 256
#define H 128
#define BS (B*S)        // 1024
#define BT (B*T)        // 1024

#define PAD 136         // padded row stride (elems) for conflict-free ldmatrix

// Scratch (device globals; no allocation allowed)
__device__ float g_src[BS * H];       // LN(source) @ W_su + b_su (fp32)
__device__ float g_A  [BS * H];       // g_src @ W1_s + b1
__device__ float g_C  [BT * H];       // g_tgt @ W1_t
__device__ __half g_th [BT * H];      // fp16 target proj

// ---------------------------------------------------------------------------
// Stage 1: per-row layernorm + projection + W1_s / W1_t projection.
// ---------------------------------------------------------------------------
__global__ __launch_bounds__(256) void norm_proj_kernel(
    const float* __restrict__ sv, const float* __restrict__ tv,
    const float* __restrict__ sng, const float* __restrict__ snb,
    const float* __restrict__ tng, const float* __restrict__ tnb,
    const float* __restrict__ Wsu, const float* __restrict__ bsu,
    const float* __restrict__ Wtp, const float* __restrict__ btp,
    const float* __restrict__ W1,  const float* __restrict__ b1)
{
    __shared__ float xn[D];
    __shared__ float pr[H];
    __shared__ float r1[8], r2[8];

    const int r = blockIdx.x;
    const bool is_src = (r < BS);
    const int row = is_src ? r : r - BS;
    const int tid = threadIdx.x;

    const float* x    = (is_src ? sv : tv) + row * D;
    const float* gv   = is_src ? sng : tng;
    const float* bv   = is_src ? snb : tnb;
    const float* W    = is_src ? Wsu : Wtp;
    const float* bias = is_src ? bsu : btp;

    float v = x[tid];
    float s1 = v, s2 = v * v;
    #pragma unroll
    for (int m = 16; m; m >>= 1) {
        s1 += __shfl_xor_sync(0xffffffffu, s1, m);
        s2 += __shfl_xor_sync(0xffffffffu, s2, m);
    }
    if ((tid & 31) == 0) { r1[tid >> 5] = s1; r2[tid >> 5] = s2; }
    __syncthreads();
    float t1 = 0.f, t2 = 0.f;
    #pragma unroll
    for (int i = 0; i < 8; ++i) { t1 += r1[i]; t2 += r2[i]; }
    const float mean = t1 * (1.0f / D);
    const float var  = t2 * (1.0f / D) - mean * mean;
    const float rs   = rsqrtf(var + 1e-5f);
    xn[tid] = (v - mean) * rs * gv[tid] + bv[tid];
    __syncthreads();

    if (tid < H) {
        float a0 = 0.f, a1 = 0.f, a2 = 0.f, a3 = 0.f;
        #pragma unroll 4
        for (int d = 0; d < D; d += 4) {
            a0 = fmaf(xn[d + 0], W[(d + 0) * H + tid], a0);
            a1 = fmaf(xn[d + 1], W[(d + 1) * H + tid], a1);
            a2 = fmaf(xn[d + 2], W[(d + 2) * H + tid], a2);
            a3 = fmaf(xn[d + 3], W[(d + 3) * H + tid], a3);
        }
        float p = (a0 + a1) + (a2 + a3) + bias[tid];
        pr[tid] = p;
        if (is_src) g_src[row * H + tid] = p;
        else        g_th[row * H + tid]  = __float2half(p);
    }
    __syncthreads();

    if (tid < H) {
        const float* Wr = W1 + (is_src ? 0 : H * H);
        float a0 = 0.f, a1 = 0.f, a2 = 0.f, a3 = 0.f;
        #pragma unroll 4
        for (int h = 0; h < H; h += 4) {
            a0 = fmaf(pr[h + 0], Wr[(h + 0) * H + tid], a0);
            a1 = fmaf(pr[h + 1], Wr[(h + 1) * H + tid], a1);
            a2 = fmaf(pr[h + 2], Wr[(h + 2) * H + tid], a2);
            a3 = fmaf(pr[h + 3], Wr[(h + 3) * H + tid], a3);
        }
        float p = (a0 + a1) + (a2 + a3) + (is_src ? b1[tid] : 0.0f);
        (is_src ? g_A : g_C)[row * H + tid] = p;
    }
}

// ---------------------------------------------------------------------------
// Stage 2: mma.sync fp16 fused kernel (single pass). grid 2048:
// CTA = (b, s, t-half). 256 threads / 8 warps, 2 CTAs/SM.
// Warp tile: 32t x 32k; CTA iteration tile: 64t x 128k; 4 iterations.
// ---------------------------------------------------------------------------
__device__ __forceinline__ void ldsm_x4(unsigned a, unsigned &r0, unsigned &r1,
                                        unsigned &r2, unsigned &r3) {
    asm volatile("ldmatrix.sync.aligned.m8n8.x4.shared.b16 {%0,%1,%2,%3}, [%4];"
        : "=r"(r0), "=r"(r1), "=r"(r2), "=r"(r3) : "r"(a));
}
__device__ __forceinline__ void ldsm_x4_t(unsigned a, unsigned &r0, unsigned &r1,
                                          unsigned &r2, unsigned &r3) {
    asm volatile("ldmatrix.sync.aligned.m8n8.x4.trans.shared.b16 {%0,%1,%2,%3}, [%4];"
        : "=r"(r0), "=r"(r1), "=r"(r2), "=r"(r3) : "r"(a));
}
__device__ __forceinline__ void mma16816(float* c, const unsigned* a,
                                         unsigned b0, unsigned b1) {
    asm volatile("mma.sync.aligned.m16n8k16.row.col.f32.f16.f16.f32 "
        "{%0,%1,%2,%3}, {%4,%5,%6,%7}, {%8,%9}, {%0,%1,%2,%3};"
        : "+f"(c[0]), "+f"(c[1]), "+f"(c[2]), "+f"(c[3])
        : "r"(a[0]), "r"(a[1]), "r"(a[2]), "r"(a[3]), "r"(b0), "r"(b1));
}

// smem byte offsets
#define TROWS 64
#define OFF_WHI 0
#define OFF_TH  (OFF_WHI + H*PAD*2)
#define OFF_SRC (OFF_TH  + TROWS*PAD*2)
#define OFF_AS  (OFF_SRC + H*4)
#define OFF_W2  (OFF_AS  + H*4)
#define OFF_PS  (OFF_W2  + H*4)
#define SMEM_BYTES (OFF_PS + TROWS*4*4)

#define NTHR 256

extern __shared__ char smem_raw[];

__global__ __launch_bounds__(NTHR, 2) void edge_main_kernel(
    const float* __restrict__ W1, const float* __restrict__ W2,
    const float* __restrict__ b2p, const int* __restrict__ mask,
    float* __restrict__ out)
{
    __half* Whi = (__half*)(smem_raw + OFF_WHI);
    float* ssrc = (float*)(smem_raw + OFF_SRC);
    float* As   = (float*)(smem_raw + OFF_AS);
    float* w2s  = (float*)(smem_raw + OFF_W2);
    float* psum = (float*)(smem_raw + OFF_PS);     // [64][4]

    unsigned smem_u32;
    asm("{ .reg .u64 t; cvta.to.shared.u64 t, %1; cvt.u32.u64 %0, t; }"
        : "=r"(smem_u32) : "l"(smem_raw));

    const int bs    = blockIdx.x >> 1;       // 0..1023
    const int thalf = blockIdx.x & 1;        // 0 or 1 (t offset 0 / 256)
    const int b     = bs >> 9;
    const int tid   = threadIdx.x;
    const int wid   = tid >> 5;
    const int lane  = tid & 31;

    if (tid < H) {
        ssrc[tid] = g_src[bs * H + tid];
        As[tid]   = g_A[bs * H + tid];
        w2s[tid]  = W2[tid];
    }
    __syncthreads();

    // Prologue: Whi[h][k] = fp16( src[h] * W1_st[h][k] )
    {
        const float4* Wst4 = (const float4*)(W1 + 2 * H * H);
        for (int i = tid; i < (H * H) / 4; i += NTHR) {
            const int h = i >> 5;
            const int c = (i & 31) * 4;
            const float sc = ssrc[h];
            float4 w = Wst4[i];
            Whi[h * PAD + c + 0] = __float2half(w.x * sc);
            Whi[h * PAD + c + 1] = __float2half(w.y * sc);
            Whi[h * PAD + c + 2] = __float2half(w.z * sc);
            Whi[h * PAD + c + 3] = __float2half(w.w * sc);
        }
    }

    const float b2v  = b2p[0];
    const float mval = mask[bs] ? 1.0f : 0.0f;

    // Warp tiling within 64t x 128k iteration tile: 2 t-groups x 4 k-groups
    const int tw0 = (wid >> 2) * 32;    // 0 or 32
    const int kq  = (wid & 3) * 32;     // k base
    const int rL = lane & 15;
    const int cL = (lane >> 4) << 3;

    for (int tt = 0; tt < 4; ++tt) {
        const int gt0 = (b << 9) + thalf * 256 + tt * TROWS;
        __syncthreads();

        // Fill Th[t][h], 64 rows (16B chunks, padded stride)
        {
            const uint4* sth = (const uint4*)(g_th + gt0 * H);
            #pragma unroll
            for (int i = tid; i < TROWS * 16; i += NTHR) {
                const int row = i >> 4;
                const int c8  = i & 15;
                *(uint4*)(smem_raw + OFF_TH + (row * PAD + c8 * 8) * 2) = sth[i];
            }
        }
        __syncthreads();

        // Mainloop: 32t x 32k per warp, K=128 in 8 steps, single fp16 pass
        float acc[2][4][4];
        #pragma unroll
        for (int f = 0; f < 2; ++f)
            #pragma unroll
            for (int g = 0; g < 4; ++g)
                #pragma unroll
                for (int j = 0; j < 4; ++j) acc[f][g][j] = 0.f;

        #pragma unroll
        for (int step = 0; step < 8; ++step) {
            const int h0 = step * 16;
            unsigned ath[2][4];
            #pragma unroll
            for (int f = 0; f < 2; ++f) {
                unsigned addr = smem_u32 + OFF_TH
                              + ((tw0 + f * 16 + rL) * PAD + h0 + cL) * 2;
                ldsm_x4(addr, ath[f][0], ath[f][1], ath[f][2], ath[f][3]);
            }
            #pragma unroll
            for (int g = 0; g < 2; ++g) {
                const int nA = kq + g * 16;
                unsigned bh0, bh1, bh2, bh3;
                unsigned baddr = smem_u32 + OFF_WHI + ((h0 + rL) * PAD + nA + cL) * 2;
                ldsm_x4_t(baddr, bh0, bh1, bh2, bh3);
                #pragma unroll
                for (int f = 0; f < 2; ++f) {
                    mma16816(acc[f][2 * g],     ath[f], bh0, bh1);
                    mma16816(acc[f][2 * g + 1], ath[f], bh2, bh3);
                }
            }
        }

        // Epilogue: + A + C, exact gelu, dot W2 over this warp's 32 k,
        // quad-reduce, psum combine, softsign, store.
        #pragma unroll
        for (int f = 0; f < 2; ++f) {
            #pragma unroll
            for (int hf = 0; hf < 2; ++hf) {
                const int t = tw0 + f * 16 + (lane >> 2) + hf * 8;
                const float2* Cr = (const float2*)(g_C + (gt0 + t) * H);
                float pt = 0.f;
                #pragma unroll
                for (int g = 0; g < 4; ++g) {
                    const int k = kq + g * 8 + (lane & 3) * 2;
                    const float2 cc = Cr[k >> 1];
                    float h0v = acc[f][g][hf * 2 + 0] + As[k]     + cc.x;
                    float h1v = acc[f][g][hf * 2 + 1] + As[k + 1] + cc.y;
                    float g0 = 0.5f * h0v * (1.0f + erff(h0v * 0.7071067811865476f));
                    float g1 = 0.5f * h1v * (1.0f + erff(h1v * 0.7071067811865476f));
                    pt = fmaf(g0, w2s[k], pt);
                    pt = fmaf(g1, w2s[k + 1], pt);
                }
                pt += __shfl_xor_sync(0xffffffffu, pt, 1);
                pt += __shfl_xor_sync(0xffffffffu, pt, 2);
                if ((lane & 3) == 0)
                    psum[t * 4 + (wid & 3)] = pt;
            }
        }
        __syncthreads();

        if (tid < TROWS) {
            const float sc = psum[tid * 4] + psum[tid * 4 + 1]
                           + psum[tid * 4 + 2] + psum[tid * 4 + 3] + b2v;
            const float e  = sc / (1.0f + fabsf(sc));
            out[bs * T + thalf * 256 + tt * TROWS + tid] = e * mval;
        }
    }
}

// ---------------------------------------------------------------------------
extern "C" void kernel_launch(void* const* d_in, const int* in_sizes, int n_in,
                              void* d_out, int out_size)
{
    const float* sv   = (const float*)d_in[0];
    const float* tv   = (const float*)d_in[1];
    const int*   mask = (const int*)d_in[2];
    const float* sng  = (const float*)d_in[3];
    const float* snb  = (const float*)d_in[4];
    const float* tng  = (const float*)d_in[5];
    const float* tnb  = (const float*)d_in[6];
    const float* Wsu  = (const float*)d_in[7];
    const float* bsu  = (const float*)d_in[8];
    const float* Wtp  = (const float*)d_in[9];
    const float* btp  = (const float*)d_in[10];
    const float* W1   = (const float*)d_in[11];
    const float* b1   = (const float*)d_in[12];
    const float* W2   = (const float*)d_in[13];
    const float* b2   = (const float*)d_in[14];
    float* out = (float*)d_out;

    norm_proj_kernel<<<BS + BT, 256>>>(sv, tv, sng, snb, tng, tnb,
                                       Wsu, bsu, Wtp, btp, W1, b1);

    cudaFuncSetAttribute(edge_main_kernel,
                         cudaFuncAttributeMaxDynamicSharedMemorySize, SMEM_BYTES);
    edge_main_kernel<<<2 * BS, NTHR, SMEM_BYTES>>>(W1, W2, b2, mask, out);
}